// round 10
// baseline (speedup 1.0000x reference)
#include <cuda_runtime.h>
#include <math.h>

// Problem constants
#define BB 64
#define LL 512
#define EE 64
#define HH 8
#define DD 8
#define NROWS (BB*LL)             // 32768
#define OUT_ELEMS (BB*LL*EE)      // 2097152

// Scratch (device globals; no allocation allowed)
__device__ float g_qh[NROWS*EE];
__device__ float g_kh[NROWS*EE];
__device__ float g_vh[NROWS*EE];
__device__ float g_ctx[NROWS*EE];
__device__ float g_zi[NROWS*HH];   // (1/Z)*0.125 per (row, head)

// ---------------------------------------------------------------------------
// Packed fp32x2 helpers (sm_103a FFMA2 path — only reachable via PTX f32x2)
// ---------------------------------------------------------------------------
__device__ __forceinline__ unsigned long long f2_pack(float lo, float hi) {
    unsigned long long r;
    asm("mov.b64 %0, {%1, %2};" : "=l"(r) : "f"(lo), "f"(hi));
    return r;
}
__device__ __forceinline__ void f2_unpack(float& lo, float& hi, unsigned long long v) {
    asm("mov.b64 {%0, %1}, %2;" : "=f"(lo), "=f"(hi) : "l"(v));
}
__device__ __forceinline__ unsigned long long f2_fma(
    unsigned long long a, unsigned long long b, unsigned long long c) {
    unsigned long long d;
    asm("fma.rn.f32x2 %0, %1, %2, %3;" : "=l"(d) : "l"(a), "l"(b), "l"(c));
    return d;
}
__device__ __forceinline__ unsigned long long f2_mul(
    unsigned long long a, unsigned long long b) {
    unsigned long long d;
    asm("mul.rn.f32x2 %0, %1, %2;" : "=l"(d) : "l"(a), "l"(b));
    return d;
}
__device__ __forceinline__ unsigned long long f2_add(
    unsigned long long a, unsigned long long b) {
    unsigned long long d;
    asm("add.rn.f32x2 %0, %1, %2;" : "=l"(d) : "l"(a), "l"(b));
    return d;
}
__device__ __forceinline__ float f2_hadd(unsigned long long v) {
    float lo, hi; f2_unpack(lo, hi, v); return lo + hi;
}
__device__ __forceinline__ float fast_ex2(float x) {
    float r;
    asm("ex2.approx.f32 %0, %1;" : "=f"(r) : "f"(x));
    return r;
}

// ---------------------------------------------------------------------------
// Kernel 1 (fused QKV proj): Y[r][o] = (sum_i X[r][i]*W[o][i] + b[o]) * oscale
// Weights hoisted to REGISTERS (o fixed per thread) -> inner loop is
// broadcast-LDS + FFMA2 only; crossbar traffic halves.
// ---------------------------------------------------------------------------
__global__ __launch_bounds__(256) void proj_kernel(
    const float* __restrict__ qin, const float* __restrict__ kin,
    const float* __restrict__ Wq, const float* __restrict__ bq,
    const float* __restrict__ Wk, const float* __restrict__ bk,
    const float* __restrict__ Wv, const float* __restrict__ bv)
{
    __shared__ float Ws[64*68];
    __shared__ float bs[64];
    __shared__ float xs[16*68];

    const float* X; const float* W; const float* bias; float* Y; float oscale;
    if (blockIdx.y == 0) {
        X = qin; W = Wq; bias = bq; Y = g_qh;
        oscale = 0.51006969919583f;   // log2(e)/sqrt(D)
    } else if (blockIdx.y == 1) {
        X = kin; W = Wk; bias = bk; Y = g_kh; oscale = 1.0f;
    } else {
        X = kin; W = Wv; bias = bv; Y = g_vh; oscale = 1.0f;
    }

    const int t = threadIdx.x;
    for (int idx = t; idx < 1024; idx += 256) {
        int o = idx >> 4, i4 = (idx & 15) << 2;
        *(float4*)&Ws[o*68 + i4] = *(const float4*)&W[o*64 + i4];
    }
    if (t < 64) bs[t] = bias[t];
    __syncthreads();

    const int o = t & 63, rg = t >> 6;
    const int row0 = blockIdx.x * 64;

    // hoist this thread's weight row into registers (one-time crossbar cost)
    unsigned long long wr[32];
    #pragma unroll
    for (int i = 0; i < 16; i++) {
        ulonglong2 w = *(const ulonglong2*)&Ws[o*68 + i*4];
        wr[2*i] = w.x; wr[2*i+1] = w.y;
    }
    const float bv_o = bs[o];

    for (int s = 0; s < 4; s++) {
        const int rbase = row0 + s*16;
        __syncthreads();
        {
            int rr = t >> 4, i4 = (t & 15) << 2;
            *(float4*)&xs[rr*68 + i4] = *(const float4*)&X[(rbase+rr)*64 + i4];
        }
        __syncthreads();
        unsigned long long a2[4] = {0ull,0ull,0ull,0ull};
        unsigned long long c2[4] = {0ull,0ull,0ull,0ull};
        #pragma unroll
        for (int i4 = 0; i4 < 16; i4++) {
            #pragma unroll
            for (int j = 0; j < 4; j++) {
                ulonglong2 x = *(const ulonglong2*)&xs[(rg*4+j)*68 + i4*4];
                a2[j] = f2_fma(wr[2*i4],   x.x, a2[j]);
                c2[j] = f2_fma(wr[2*i4+1], x.y, c2[j]);
            }
        }
        #pragma unroll
        for (int j = 0; j < 4; j++)
            Y[(rbase+rg*4+j)*64 + o] = (f2_hadd(f2_add(a2[j], c2[j])) + bv_o) * oscale;
    }
}

// ---------------------------------------------------------------------------
// Kernel 2a: attention pass 1. Block=(q-tile 64, batch), 256 threads =
// (16 qg of 4 queries, 8 heads, 2 m-halves). Each half covers 32 m per chunk;
// cross-half Z/ctx reduction once per block via reused K/V smem (stride 37,
// conflict-free). Single pass: Z + unnormalized ctx -> normalized ctx + zi.
// ---------------------------------------------------------------------------
__global__ __launch_bounds__(256, 3) void attn1_kernel()
{
    __shared__ float kv[2*64*68];
    float* ks = kv;
    float* vs = kv + 64*68;

    const int b  = blockIdx.y;
    const int q0 = blockIdx.x * 64;
    const int t  = threadIdx.x;
    const int qg = (t >> 3) & 15, h = t & 7, mh = t >> 7;

    unsigned long long qp[4][4];
    #pragma unroll
    for (int j = 0; j < 4; j++) {
        const ulonglong2* qb =
            (const ulonglong2*)(g_qh + (size_t)(b*LL + q0 + qg*4 + j) * EE + h*8);
        ulonglong2 a = qb[0], c = qb[1];
        qp[j][0] = a.x; qp[j][1] = a.y; qp[j][2] = c.x; qp[j][3] = c.y;
    }

    float Z[4] = {0.f, 0.f, 0.f, 0.f};
    unsigned long long cx[4][4] = {{0ull,0ull,0ull,0ull},{0ull,0ull,0ull,0ull},
                                   {0ull,0ull,0ull,0ull},{0ull,0ull,0ull,0ull}};

    for (int c = 0; c < 8; c++) {
        __syncthreads();
        const float* kb = g_kh + (size_t)(b*LL + c*64) * EE;
        const float* vb = g_vh + (size_t)(b*LL + c*64) * EE;
        for (int idx = t; idx < 1024; idx += 256) {
            int m = idx >> 4, i4 = (idx & 15) << 2;
            *(float4*)&ks[m*68 + i4] = *(const float4*)(kb + m*EE + i4);
            *(float4*)&vs[m*68 + i4] = *(const float4*)(vb + m*EE + i4);
        }
        __syncthreads();
        const int m0 = mh * 32;
        #pragma unroll 2
        for (int mi = 0; mi < 32; mi++) {
            const int m = m0 + mi;
            ulonglong2 ka = *(const ulonglong2*)&ks[m*68 + h*8];
            ulonglong2 kc = *(const ulonglong2*)&ks[m*68 + h*8 + 4];
            ulonglong2 va = *(const ulonglong2*)&vs[m*68 + h*8];
            ulonglong2 vc = *(const ulonglong2*)&vs[m*68 + h*8 + 4];
            #pragma unroll
            for (int j = 0; j < 4; j++) {
                unsigned long long acc = f2_mul(qp[j][0], ka.x);
                acc = f2_fma(qp[j][1], ka.y, acc);
                acc = f2_fma(qp[j][2], kc.x, acc);
                acc = f2_fma(qp[j][3], kc.y, acc);
                float e = fast_ex2(f2_hadd(acc));
                Z[j] += e;
                unsigned long long pp = f2_pack(e, e);
                cx[j][0] = f2_fma(pp, va.x, cx[j][0]);
                cx[j][1] = f2_fma(pp, va.y, cx[j][1]);
                cx[j][2] = f2_fma(pp, vc.x, cx[j][2]);
                cx[j][3] = f2_fma(pp, vc.y, cx[j][3]);
            }
        }
    }

    // ---- cross-half reduction (reuse kv smem; stride 37 conflict-free) ----
    __syncthreads();
    float* red = kv;
    if (mh == 1) {
        const int base = (t & 127) * 37;
        #pragma unroll
        for (int j = 0; j < 4; j++) {
            red[base + j] = Z[j];
            #pragma unroll
            for (int i = 0; i < 4; i++) {
                float lo, hi; f2_unpack(lo, hi, cx[j][i]);
                red[base + 4 + j*8 + i*2]     = lo;
                red[base + 4 + j*8 + i*2 + 1] = hi;
            }
        }
    }
    __syncthreads();
    if (mh == 0) {
        const int base = t * 37;
        #pragma unroll
        for (int j = 0; j < 4; j++) {
            float Zt = Z[j] + red[base + j];
            float zi = 1.0f / Zt;
            const size_t row = (size_t)(b*LL + q0 + qg*4 + j);
            float* cb = g_ctx + row * EE + h*8;
            float o[8];
            #pragma unroll
            for (int i = 0; i < 4; i++) {
                float lo, hi; f2_unpack(lo, hi, cx[j][i]);
                o[2*i]   = (lo + red[base + 4 + j*8 + i*2])     * zi;
                o[2*i+1] = (hi + red[base + 4 + j*8 + i*2 + 1]) * zi;
            }
            *(float4*)(cb)     = make_float4(o[0], o[1], o[2], o[3]);
            *(float4*)(cb + 4) = make_float4(o[4], o[5], o[6], o[7]);
            g_zi[row*HH + h] = zi * 0.125f;
        }
    }
}

// ---------------------------------------------------------------------------
// Tail: FUSED attn2 + epilogue in one launch (independent after attn1).
// Blocks alternate roles by parity.
// ---------------------------------------------------------------------------

// attn2 body: 256 threads; thread owns ONE query (all 8 heads), 4 threads
// per query striding m by 4. K rows broadcast from shared; no shuffles.
__device__ __forceinline__ void attn2_body(float* sm, float* __restrict__ attn_out,
                                           int bx)
{
    float* ks = sm;               // 64*68
    float* aw = sm + 64*68;       // 64*65

    const int b  = bx >> 3;
    const int q0 = (bx & 7) * 64;
    const int t  = threadIdx.x;
    const int q       = t & 63;   // local query
    const int quarter = t >> 6;   // m residue (uniform per warp)

    unsigned long long qp[32];
    {
        const ulonglong2* qb = (const ulonglong2*)(g_qh + (size_t)(b*LL + q0 + q) * EE);
        #pragma unroll
        for (int i = 0; i < 16; i++) {
            ulonglong2 v = qb[i];
            qp[2*i] = v.x; qp[2*i+1] = v.y;
        }
    }
    unsigned long long ziP[4];
    {
        const float* zr = g_zi + (size_t)(b*LL + q0 + q) * HH;
        float4 z0 = *(const float4*)zr, z1 = *(const float4*)(zr + 4);
        ziP[0] = f2_pack(z0.x, z0.y); ziP[1] = f2_pack(z0.z, z0.w);
        ziP[2] = f2_pack(z1.x, z1.y); ziP[3] = f2_pack(z1.z, z1.w);
    }

    for (int c = 0; c < 8; c++) {
        __syncthreads();   // aw drained + ks consumed from previous chunk
        const float* kb = g_kh + (size_t)(b*LL + c*64) * EE;
        for (int idx = t; idx < 1024; idx += 256) {
            int m = idx >> 4, i4 = (idx & 15) << 2;
            *(float4*)&ks[m*68 + i4] = *(const float4*)(kb + m*EE + i4);
        }
        __syncthreads();

        #pragma unroll 2
        for (int mm = 0; mm < 16; mm++) {
            const int m = mm*4 + quarter;     // uniform per warp
            float e[8];
            #pragma unroll
            for (int hh = 0; hh < 8; hh++) {
                const ulonglong2* kr = (const ulonglong2*)&ks[m*68 + hh*8];
                ulonglong2 k0 = kr[0], k1 = kr[1];
                unsigned long long acc = f2_mul(qp[4*hh], k0.x);
                acc = f2_fma(qp[4*hh+1], k0.y, acc);
                acc = f2_fma(qp[4*hh+2], k1.x, acc);
                acc = f2_fma(qp[4*hh+3], k1.y, acc);
                e[hh] = fast_ex2(f2_hadd(acc));
            }
            unsigned long long acc = f2_mul(f2_pack(e[0], e[1]), ziP[0]);
            acc = f2_fma(f2_pack(e[2], e[3]), ziP[1], acc);
            acc = f2_fma(f2_pack(e[4], e[5]), ziP[2], acc);
            acc = f2_fma(f2_pack(e[6], e[7]), ziP[3], acc);
            aw[m*65 + q] = f2_hadd(acc);
        }
        __syncthreads();

        // coalesced copy-out: lanes span m for fixed q
        float* ob = attn_out + ((size_t)(b*LL) + q0) * LL + c*64;
        #pragma unroll
        for (int g = 0; g < 4; g++) {
            int idx = t + g*256;
            int mq = idx & 15, qq = idx >> 4;
            float4 v = make_float4(aw[(mq*4+0)*65 + qq], aw[(mq*4+1)*65 + qq],
                                   aw[(mq*4+2)*65 + qq], aw[(mq*4+3)*65 + qq]);
            *(float4*)(ob + (size_t)qq*LL + mq*4) = v;
        }
    }
}

// epilogue body
__device__ __forceinline__ void epilogue_body(float* sm,
    const float* __restrict__ prev,
    const float* __restrict__ Wo, const float* __restrict__ bo,
    const float* __restrict__ ln1g, const float* __restrict__ ln1b,
    const float* __restrict__ W1, const float* __restrict__ b1,
    const float* __restrict__ W2, const float* __restrict__ b2,
    const float* __restrict__ ln2g, const float* __restrict__ ln2b,
    float* __restrict__ out, int bx)
{
    float* WoS = sm;                 // 64*68
    float* W1S = WoS + 64*68;
    float* W2S = W1S + 64*68;
    float* xs  = W2S + 64*68;        // 16*68
    float* ys  = xs + 16*68;         // 16*68
    float* mvS = ys + 16*68;         // 32
    float* prm = mvS + 32;           // 7*64

    const int t = threadIdx.x;
    for (int idx = t; idx < 1024; idx += 256) {
        int o = idx >> 4, i4 = (idx & 15) << 2;
        *(float4*)&WoS[o*68 + i4] = *(const float4*)&Wo[o*64 + i4];
        *(float4*)&W1S[o*68 + i4] = *(const float4*)&W1[o*64 + i4];
        *(float4*)&W2S[o*68 + i4] = *(const float4*)&W2[o*64 + i4];
    }
    if (t < 64) {
        prm[t]       = bo[t];   prm[64 + t]  = b1[t];  prm[128 + t] = b2[t];
        prm[192 + t] = ln1g[t]; prm[256 + t] = ln1b[t];
        prm[320 + t] = ln2g[t]; prm[384 + t] = ln2b[t];
    }

    const int o = t & 63, rg = t >> 6;
    const int row0 = bx * 64;
    const int rrS = t >> 4, cS = t & 15;

    for (int s = 0; s < 4; s++) {
        const int rbase = row0 + s*16;
        __syncthreads();
        {
            int rr = t >> 4, i4 = (t & 15) << 2;
            *(float4*)&xs[rr*68 + i4] = *(const float4*)&g_ctx[(rbase+rr)*EE + i4];
        }
        __syncthreads();

        // GEMM1: mha = ctx @ Wo^T + bo, + prev
        unsigned long long a2[4] = {0ull,0ull,0ull,0ull};
        unsigned long long c2[4] = {0ull,0ull,0ull,0ull};
        #pragma unroll
        for (int i4 = 0; i4 < 64; i4 += 4) {
            ulonglong2 w = *(const ulonglong2*)&WoS[o*68 + i4];
            #pragma unroll
            for (int j = 0; j < 4; j++) {
                ulonglong2 x = *(const ulonglong2*)&xs[(rg*4+j)*68 + i4];
                a2[j] = f2_fma(w.x, x.x, a2[j]);
                c2[j] = f2_fma(w.y, x.y, c2[j]);
            }
        }
        #pragma unroll
        for (int j = 0; j < 4; j++) {
            float acc = f2_hadd(f2_add(a2[j], c2[j])) + prm[o];
            acc += prev[(rbase+rg*4+j)*EE + o];
            ys[(rg*4+j)*68 + o] = acc;
        }
        __syncthreads();

        // LN1 stats
        {
            float s1 = 0.f, s2 = 0.f;
            #pragma unroll
            for (int ii = 0; ii < 4; ii++) {
                float v = ys[rrS*68 + cS + ii*16]; s1 += v; s2 += v*v;
            }
            #pragma unroll
            for (int off = 8; off; off >>= 1) {
                s1 += __shfl_xor_sync(0xffffffffu, s1, off, 16);
                s2 += __shfl_xor_sync(0xffffffffu, s2, off, 16);
            }
            if (cS == 0) {
                float mu = s1 * (1.0f/64.0f);
                float var = s2 * (1.0f/64.0f) - mu*mu;
                mvS[rrS*2]     = mu;
                mvS[rrS*2 + 1] = rsqrtf(var + 1e-5f);
            }
        }
        __syncthreads();

        float xr[4];
        #pragma unroll
        for (int j = 0; j < 4; j++) {
            int rr = rg*4 + j;
            float v = ys[rr*68 + o];
            float xn = (v - mvS[rr*2]) * mvS[rr*2+1] * prm[192 + o] + prm[256 + o];
            xr[j] = xn;
            xs[rr*68 + o] = xn;
        }
        __syncthreads();

        // GEMM2: h1 = relu(x @ W1^T + b1) -> ys
        #pragma unroll
        for (int j = 0; j < 4; j++) { a2[j] = 0ull; c2[j] = 0ull; }
        #pragma unroll
        for (int i4 = 0; i4 < 64; i4 += 4) {
            ulonglong2 w = *(const ulonglong2*)&W1S[o*68 + i4];
            #pragma unroll
            for (int j = 0; j < 4; j++) {
                ulonglong2 x = *(const ulonglong2*)&xs[(rg*4+j)*68 + i4];
                a2[j] = f2_fma(w.x, x.x, a2[j]);
                c2[j] = f2_fma(w.y, x.y, c2[j]);
            }
        }
        #pragma unroll
        for (int j = 0; j < 4; j++)
            ys[(rg*4+j)*68 + o] = fmaxf(f2_hadd(f2_add(a2[j], c2[j])) + prm[64 + o], 0.f);
        __syncthreads();

        // GEMM3: f = h1 @ W2^T + b2 + x
        #pragma unroll
        for (int j = 0; j < 4; j++) { a2[j] = 0ull; c2[j] = 0ull; }
        #pragma unroll
        for (int i4 = 0; i4 < 64; i4 += 4) {
            ulonglong2 w = *(const ulonglong2*)&W2S[o*68 + i4];
            #pragma unroll
            for (int j = 0; j < 4; j++) {
                ulonglong2 x = *(const ulonglong2*)&ys[(rg*4+j)*68 + i4];
                a2[j] = f2_fma(w.x, x.x, a2[j]);
                c2[j] = f2_fma(w.y, x.y, c2[j]);
            }
        }
        float fr[4];
        #pragma unroll
        for (int j = 0; j < 4; j++) {
            fr[j] = f2_hadd(f2_add(a2[j], c2[j])) + prm[128 + o] + xr[j];
            xs[(rg*4+j)*68 + o] = fr[j];
        }
        __syncthreads();

        // LN2 stats
        {
            float s1 = 0.f, s2 = 0.f;
            #pragma unroll
            for (int ii = 0; ii < 4; ii++) {
                float v = xs[rrS*68 + cS + ii*16]; s1 += v; s2 += v*v;
            }
            #pragma unroll
            for (int off = 8; off; off >>= 1) {
                s1 += __shfl_xor_sync(0xffffffffu, s1, off, 16);
                s2 += __shfl_xor_sync(0xffffffffu, s2, off, 16);
            }
            if (cS == 0) {
                float mu = s1 * (1.0f/64.0f);
                float var = s2 * (1.0f/64.0f) - mu*mu;
                mvS[rrS*2]     = mu;
                mvS[rrS*2 + 1] = rsqrtf(var + 1e-5f);
            }
        }
        __syncthreads();

        #pragma unroll
        for (int j = 0; j < 4; j++) {
            int rr = rg*4 + j;
            out[(rbase+rr)*EE + o] =
                (fr[j] - mvS[rr*2]) * mvS[rr*2+1] * prm[320 + o] + prm[384 + o];
        }
    }
}

__global__ __launch_bounds__(256) void tail_kernel(
    float* __restrict__ attn_out,
    const float* __restrict__ prev,
    const float* __restrict__ Wo, const float* __restrict__ bo,
    const float* __restrict__ ln1g, const float* __restrict__ ln1b,
    const float* __restrict__ W1, const float* __restrict__ b1,
    const float* __restrict__ W2, const float* __restrict__ b2,
    const float* __restrict__ ln2g, const float* __restrict__ ln2b,
    float* __restrict__ out)
{
    extern __shared__ float sm[];
    const int bid = blockIdx.x;
    if (bid & 1) {
        epilogue_body(sm, prev, Wo, bo, ln1g, ln1b, W1, b1, W2, b2,
                      ln2g, ln2b, out, bid >> 1);
    } else {
        attn2_body(sm, attn_out, bid >> 1);
    }
}

// ---------------------------------------------------------------------------
extern "C" void kernel_launch(void* const* d_in, const int* in_sizes, int n_in,
                              void* d_out, int out_size)
{
    const float* q    = (const float*)d_in[0];
    const float* k    = (const float*)d_in[1];
    const float* prev = (const float*)d_in[2];
    const float* Wq   = (const float*)d_in[3];
    const float* bq   = (const float*)d_in[4];
    const float* Wk   = (const float*)d_in[5];
    const float* bk   = (const float*)d_in[6];
    const float* Wv   = (const float*)d_in[7];
    const float* bv   = (const float*)d_in[8];
    const float* Wo   = (const float*)d_in[9];
    const float* bo   = (const float*)d_in[10];
    const float* ln1g = (const float*)d_in[11];
    const float* ln1b = (const float*)d_in[12];
    const float* W1   = (const float*)d_in[13];
    const float* b1   = (const float*)d_in[14];
    const float* W2   = (const float*)d_in[15];
    const float* b2   = (const float*)d_in[16];
    const float* ln2g = (const float*)d_in[17];
    const float* ln2b = (const float*)d_in[18];

    float* out      = (float*)d_out;
    float* attn_out = out + OUT_ELEMS;

    const int TAIL_SMEM = (3*64*68 + 2*16*68 + 32 + 7*64)*4; // 62848 B
    cudaFuncSetAttribute(tail_kernel,
        cudaFuncAttributeMaxDynamicSharedMemorySize, TAIL_SMEM);

    proj_kernel<<<dim3(NROWS/64, 3), 256>>>(q, k, Wq, bq, Wk, bk, Wv, bv);

    attn1_kernel<<<dim3(LL/64, BB), 256>>>();

    tail_kernel<<<2*(NROWS/64), 256, TAIL_SMEM>>>(
        attn_out, prev, Wo, bo, ln1g, ln1b, W1, b1, W2, b2, ln2g, ln2b, out);
}

// round 13
// speedup vs baseline: 1.2459x; 1.2459x over previous
#include <cuda_runtime.h>
#include <math.h>

// Problem constants
#define BB 64
#define LL 512
#define EE 64
#define HH 8
#define DD 8
#define NROWS (BB*LL)             // 32768
#define OUT_ELEMS (BB*LL*EE)      // 2097152

// Scratch (device globals; no allocation allowed)
__device__ float g_qh[NROWS*EE];
__device__ float g_kh[NROWS*EE];
__device__ float g_vh[NROWS*EE];
__device__ float g_ctx[NROWS*EE];
__device__ float g_zi[NROWS*HH];   // (1/Z)*0.125 per (row, head)

// ---------------------------------------------------------------------------
// Packed fp32x2 helpers (sm_103a FFMA2 path — only reachable via PTX f32x2)
// ---------------------------------------------------------------------------
__device__ __forceinline__ unsigned long long f2_pack(float lo, float hi) {
    unsigned long long r;
    asm("mov.b64 %0, {%1, %2};" : "=l"(r) : "f"(lo), "f"(hi));
    return r;
}
__device__ __forceinline__ void f2_unpack(float& lo, float& hi, unsigned long long v) {
    asm("mov.b64 {%0, %1}, %2;" : "=f"(lo), "=f"(hi) : "l"(v));
}
__device__ __forceinline__ unsigned long long f2_fma(
    unsigned long long a, unsigned long long b, unsigned long long c) {
    unsigned long long d;
    asm("fma.rn.f32x2 %0, %1, %2, %3;" : "=l"(d) : "l"(a), "l"(b), "l"(c));
    return d;
}
__device__ __forceinline__ unsigned long long f2_mul(
    unsigned long long a, unsigned long long b) {
    unsigned long long d;
    asm("mul.rn.f32x2 %0, %1, %2;" : "=l"(d) : "l"(a), "l"(b));
    return d;
}
__device__ __forceinline__ unsigned long long f2_add(
    unsigned long long a, unsigned long long b) {
    unsigned long long d;
    asm("add.rn.f32x2 %0, %1, %2;" : "=l"(d) : "l"(a), "l"(b));
    return d;
}
__device__ __forceinline__ float f2_hadd(unsigned long long v) {
    float lo, hi; f2_unpack(lo, hi, v); return lo + hi;
}
__device__ __forceinline__ float fast_ex2(float x) {
    float r;
    asm("ex2.approx.f32 %0, %1;" : "=f"(r) : "f"(x));
    return r;
}

// ---------------------------------------------------------------------------
// Kernel 1 (fused QKV proj): Y[r][o] = (sum_i X[r][i]*W[o][i] + b[o]) * oscale
// Weights hoisted to REGISTERS (o fixed per thread) -> inner loop is
// broadcast-LDS + FFMA2 only.  (R10-measured: 39.4us)
// ---------------------------------------------------------------------------
__global__ __launch_bounds__(256) void proj_kernel(
    const float* __restrict__ qin, const float* __restrict__ kin,
    const float* __restrict__ Wq, const float* __restrict__ bq,
    const float* __restrict__ Wk, const float* __restrict__ bk,
    const float* __restrict__ Wv, const float* __restrict__ bv)
{
    __shared__ float Ws[64*68];
    __shared__ float bs[64];
    __shared__ float xs[16*68];

    const float* X; const float* W; const float* bias; float* Y; float oscale;
    if (blockIdx.y == 0) {
        X = qin; W = Wq; bias = bq; Y = g_qh;
        oscale = 0.51006969919583f;   // log2(e)/sqrt(D)
    } else if (blockIdx.y == 1) {
        X = kin; W = Wk; bias = bk; Y = g_kh; oscale = 1.0f;
    } else {
        X = kin; W = Wv; bias = bv; Y = g_vh; oscale = 1.0f;
    }

    const int t = threadIdx.x;
    for (int idx = t; idx < 1024; idx += 256) {
        int o = idx >> 4, i4 = (idx & 15) << 2;
        *(float4*)&Ws[o*68 + i4] = *(const float4*)&W[o*64 + i4];
    }
    if (t < 64) bs[t] = bias[t];
    __syncthreads();

    const int o = t & 63, rg = t >> 6;
    const int row0 = blockIdx.x * 64;

    unsigned long long wr[32];
    #pragma unroll
    for (int i = 0; i < 16; i++) {
        ulonglong2 w = *(const ulonglong2*)&Ws[o*68 + i*4];
        wr[2*i] = w.x; wr[2*i+1] = w.y;
    }
    const float bv_o = bs[o];

    for (int s = 0; s < 4; s++) {
        const int rbase = row0 + s*16;
        __syncthreads();
        {
            int rr = t >> 4, i4 = (t & 15) << 2;
            *(float4*)&xs[rr*68 + i4] = *(const float4*)&X[(rbase+rr)*64 + i4];
        }
        __syncthreads();
        unsigned long long a2[4] = {0ull,0ull,0ull,0ull};
        unsigned long long c2[4] = {0ull,0ull,0ull,0ull};
        #pragma unroll
        for (int i4 = 0; i4 < 16; i4++) {
            #pragma unroll
            for (int j = 0; j < 4; j++) {
                ulonglong2 x = *(const ulonglong2*)&xs[(rg*4+j)*68 + i4*4];
                a2[j] = f2_fma(wr[2*i4],   x.x, a2[j]);
                c2[j] = f2_fma(wr[2*i4+1], x.y, c2[j]);
            }
        }
        #pragma unroll
        for (int j = 0; j < 4; j++)
            Y[(rbase+rg*4+j)*64 + o] = (f2_hadd(f2_add(a2[j], c2[j])) + bv_o) * oscale;
    }
}

// ---------------------------------------------------------------------------
// Kernel 2a: attention pass 1 — EXACT R3 structure (measured ~150us).
// Block=(q-tile 64, batch), 128 threads, thread = (qg of 4 queries, head).
// Single pass: Z + unnormalized ctx; writes normalized ctx and zi*0.125.
// ---------------------------------------------------------------------------
__global__ __launch_bounds__(128) void attn1_kernel()
{
    __shared__ float ks[64*68];
    __shared__ float vs[64*68];

    const int b  = blockIdx.y;
    const int q0 = blockIdx.x * 64;
    const int t  = threadIdx.x;
    const int qg = t >> 3, h = t & 7;    // qg 0..15 (4 q each), h 0..7

    unsigned long long qp[4][4];
    #pragma unroll
    for (int j = 0; j < 4; j++) {
        const ulonglong2* qb =
            (const ulonglong2*)(g_qh + (size_t)(b*LL + q0 + qg*4 + j) * EE + h*8);
        ulonglong2 a = qb[0], c = qb[1];
        qp[j][0] = a.x; qp[j][1] = a.y; qp[j][2] = c.x; qp[j][3] = c.y;
    }

    float Z[4] = {0.f, 0.f, 0.f, 0.f};
    unsigned long long cx[4][4] = {{0ull,0ull,0ull,0ull},{0ull,0ull,0ull,0ull},
                                   {0ull,0ull,0ull,0ull},{0ull,0ull,0ull,0ull}};

    for (int c = 0; c < 8; c++) {
        __syncthreads();
        const float* kb = g_kh + (size_t)(b*LL + c*64) * EE;
        const float* vb = g_vh + (size_t)(b*LL + c*64) * EE;
        for (int idx = t; idx < 1024; idx += 128) {
            int m = idx >> 4, i4 = (idx & 15) << 2;
            *(float4*)&ks[m*68 + i4] = *(const float4*)(kb + m*EE + i4);
            *(float4*)&vs[m*68 + i4] = *(const float4*)(vb + m*EE + i4);
        }
        __syncthreads();
        #pragma unroll 2
        for (int m = 0; m < 64; m++) {
            ulonglong2 ka = *(const ulonglong2*)&ks[m*68 + h*8];
            ulonglong2 kc = *(const ulonglong2*)&ks[m*68 + h*8 + 4];
            ulonglong2 va = *(const ulonglong2*)&vs[m*68 + h*8];
            ulonglong2 vc = *(const ulonglong2*)&vs[m*68 + h*8 + 4];
            #pragma unroll
            for (int j = 0; j < 4; j++) {
                unsigned long long acc = f2_mul(qp[j][0], ka.x);
                acc = f2_fma(qp[j][1], ka.y, acc);
                acc = f2_fma(qp[j][2], kc.x, acc);
                acc = f2_fma(qp[j][3], kc.y, acc);
                float e = fast_ex2(f2_hadd(acc));
                Z[j] += e;
                unsigned long long pp = f2_pack(e, e);
                cx[j][0] = f2_fma(pp, va.x, cx[j][0]);
                cx[j][1] = f2_fma(pp, va.y, cx[j][1]);
                cx[j][2] = f2_fma(pp, vc.x, cx[j][2]);
                cx[j][3] = f2_fma(pp, vc.y, cx[j][3]);
            }
        }
    }

    #pragma unroll
    for (int j = 0; j < 4; j++) {
        float zi = 1.0f / Z[j];
        const size_t row = (size_t)(b*LL + q0 + qg*4 + j);
        float* cb = g_ctx + row * EE + h*8;
        float o[8];
        #pragma unroll
        for (int i = 0; i < 4; i++) {
            float lo, hi; f2_unpack(lo, hi, cx[j][i]);
            o[2*i] = lo * zi; o[2*i+1] = hi * zi;
        }
        *(float4*)(cb)     = make_float4(o[0], o[1], o[2], o[3]);
        *(float4*)(cb + 4) = make_float4(o[4], o[5], o[6], o[7]);
        g_zi[row*HH + h] = zi * 0.125f;
    }
}

// ---------------------------------------------------------------------------
// Tail: FUSED attn2 + epilogue in one launch (independent after attn1).
// Blocks alternate roles by parity. (R7-measured ~147us combined)
// ---------------------------------------------------------------------------

__device__ __forceinline__ void attn2_body(float* sm, float* __restrict__ attn_out,
                                           int bx)
{
    float* ks = sm;               // 64*68
    float* aw = sm + 64*68;       // 64*65

    const int b  = bx >> 3;
    const int q0 = (bx & 7) * 64;
    const int t  = threadIdx.x;
    const int q       = t & 63;   // local query
    const int quarter = t >> 6;   // m residue (uniform per warp)

    unsigned long long qp[32];
    {
        const ulonglong2* qb = (const ulonglong2*)(g_qh + (size_t)(b*LL + q0 + q) * EE);
        #pragma unroll
        for (int i = 0; i < 16; i++) {
            ulonglong2 v = qb[i];
            qp[2*i] = v.x; qp[2*i+1] = v.y;
        }
    }
    unsigned long long ziP[4];
    {
        const float* zr = g_zi + (size_t)(b*LL + q0 + q) * HH;
        float4 z0 = *(const float4*)zr, z1 = *(const float4*)(zr + 4);
        ziP[0] = f2_pack(z0.x, z0.y); ziP[1] = f2_pack(z0.z, z0.w);
        ziP[2] = f2_pack(z1.x, z1.y); ziP[3] = f2_pack(z1.z, z1.w);
    }

    for (int c = 0; c < 8; c++) {
        __syncthreads();
        const float* kb = g_kh + (size_t)(b*LL + c*64) * EE;
        for (int idx = t; idx < 1024; idx += 256) {
            int m = idx >> 4, i4 = (idx & 15) << 2;
            *(float4*)&ks[m*68 + i4] = *(const float4*)(kb + m*EE + i4);
        }
        __syncthreads();

        #pragma unroll 2
        for (int mm = 0; mm < 16; mm++) {
            const int m = mm*4 + quarter;     // uniform per warp
            float e[8];
            #pragma unroll
            for (int hh = 0; hh < 8; hh++) {
                const ulonglong2* kr = (const ulonglong2*)&ks[m*68 + hh*8];
                ulonglong2 k0 = kr[0], k1 = kr[1];
                unsigned long long acc = f2_mul(qp[4*hh], k0.x);
                acc = f2_fma(qp[4*hh+1], k0.y, acc);
                acc = f2_fma(qp[4*hh+2], k1.x, acc);
                acc = f2_fma(qp[4*hh+3], k1.y, acc);
                e[hh] = fast_ex2(f2_hadd(acc));
            }
            unsigned long long acc = f2_mul(f2_pack(e[0], e[1]), ziP[0]);
            acc = f2_fma(f2_pack(e[2], e[3]), ziP[1], acc);
            acc = f2_fma(f2_pack(e[4], e[5]), ziP[2], acc);
            acc = f2_fma(f2_pack(e[6], e[7]), ziP[3], acc);
            aw[m*65 + q] = f2_hadd(acc);
        }
        __syncthreads();

        float* ob = attn_out + ((size_t)(b*LL) + q0) * LL + c*64;
        #pragma unroll
        for (int g = 0; g < 4; g++) {
            int idx = t + g*256;
            int mq = idx & 15, qq = idx >> 4;
            float4 v = make_float4(aw[(mq*4+0)*65 + qq], aw[(mq*4+1)*65 + qq],
                                   aw[(mq*4+2)*65 + qq], aw[(mq*4+3)*65 + qq]);
            *(float4*)(ob + (size_t)qq*LL + mq*4) = v;
        }
    }
}

__device__ __forceinline__ void epilogue_body(float* sm,
    const float* __restrict__ prev,
    const float* __restrict__ Wo, const float* __restrict__ bo,
    const float* __restrict__ ln1g, const float* __restrict__ ln1b,
    const float* __restrict__ W1, const float* __restrict__ b1,
    const float* __restrict__ W2, const float* __restrict__ b2,
    const float* __restrict__ ln2g, const float* __restrict__ ln2b,
    float* __restrict__ out, int bx)
{
    float* WoS = sm;                 // 64*68
    float* W1S = WoS + 64*68;
    float* W2S = W1S + 64*68;
    float* xs  = W2S + 64*68;        // 16*68
    float* ys  = xs + 16*68;         // 16*68
    float* mvS = ys + 16*68;         // 32
    float* prm = mvS + 32;           // 7*64

    const int t = threadIdx.x;
    for (int idx = t; idx < 1024; idx += 256) {
        int o = idx >> 4, i4 = (idx & 15) << 2;
        *(float4*)&WoS[o*68 + i4] = *(const float4*)&Wo[o*64 + i4];
        *(float4*)&W1S[o*68 + i4] = *(const float4*)&W1[o*64 + i4];
        *(float4*)&W2S[o*68 + i4] = *(const float4*)&W2[o*64 + i4];
    }
    if (t < 64) {
        prm[t]       = bo[t];   prm[64 + t]  = b1[t];  prm[128 + t] = b2[t];
        prm[192 + t] = ln1g[t]; prm[256 + t] = ln1b[t];
        prm[320 + t] = ln2g[t]; prm[384 + t] = ln2b[t];
    }

    const int o = t & 63, rg = t >> 6;
    const int row0 = bx * 64;
    const int rrS = t >> 4, cS = t & 15;

    for (int s = 0; s < 4; s++) {
        const int rbase = row0 + s*16;
        __syncthreads();
        {
            int rr = t >> 4, i4 = (t & 15) << 2;
            *(float4*)&xs[rr*68 + i4] = *(const float4*)&g_ctx[(rbase+rr)*EE + i4];
        }
        __syncthreads();

        unsigned long long a2[4] = {0ull,0ull,0ull,0ull};
        unsigned long long c2[4] = {0ull,0ull,0ull,0ull};
        #pragma unroll
        for (int i4 = 0; i4 < 64; i4 += 4) {
            ulonglong2 w = *(const ulonglong2*)&WoS[o*68 + i4];
            #pragma unroll
            for (int j = 0; j < 4; j++) {
                ulonglong2 x = *(const ulonglong2*)&xs[(rg*4+j)*68 + i4];
                a2[j] = f2_fma(w.x, x.x, a2[j]);
                c2[j] = f2_fma(w.y, x.y, c2[j]);
            }
        }
        #pragma unroll
        for (int j = 0; j < 4; j++) {
            float acc = f2_hadd(f2_add(a2[j], c2[j])) + prm[o];
            acc += prev[(rbase+rg*4+j)*EE + o];
            ys[(rg*4+j)*68 + o] = acc;
        }
        __syncthreads();

        {
            float s1 = 0.f, s2 = 0.f;
            #pragma unroll
            for (int ii = 0; ii < 4; ii++) {
                float v = ys[rrS*68 + cS + ii*16]; s1 += v; s2 += v*v;
            }
            #pragma unroll
            for (int off = 8; off; off >>= 1) {
                s1 += __shfl_xor_sync(0xffffffffu, s1, off, 16);
                s2 += __shfl_xor_sync(0xffffffffu, s2, off, 16);
            }
            if (cS == 0) {
                float mu = s1 * (1.0f/64.0f);
                float var = s2 * (1.0f/64.0f) - mu*mu;
                mvS[rrS*2]     = mu;
                mvS[rrS*2 + 1] = rsqrtf(var + 1e-5f);
            }
        }
        __syncthreads();

        float xr[4];
        #pragma unroll
        for (int j = 0; j < 4; j++) {
            int rr = rg*4 + j;
            float v = ys[rr*68 + o];
            float xn = (v - mvS[rr*2]) * mvS[rr*2+1] * prm[192 + o] + prm[256 + o];
            xr[j] = xn;
            xs[rr*68 + o] = xn;
        }
        __syncthreads();

        #pragma unroll
        for (int j = 0; j < 4; j++) { a2[j] = 0ull; c2[j] = 0ull; }
        #pragma unroll
        for (int i4 = 0; i4 < 64; i4 += 4) {
            ulonglong2 w = *(const ulonglong2*)&W1S[o*68 + i4];
            #pragma unroll
            for (int j = 0; j < 4; j++) {
                ulonglong2 x = *(const ulonglong2*)&xs[(rg*4+j)*68 + i4];
                a2[j] = f2_fma(w.x, x.x, a2[j]);
                c2[j] = f2_fma(w.y, x.y, c2[j]);
            }
        }
        #pragma unroll
        for (int j = 0; j < 4; j++)
            ys[(rg*4+j)*68 + o] = fmaxf(f2_hadd(f2_add(a2[j], c2[j])) + prm[64 + o], 0.f);
        __syncthreads();

        #pragma unroll
        for (int j = 0; j < 4; j++) { a2[j] = 0ull; c2[j] = 0ull; }
        #pragma unroll
        for (int i4 = 0; i4 < 64; i4 += 4) {
            ulonglong2 w = *(const ulonglong2*)&W2S[o*68 + i4];
            #pragma unroll
            for (int j = 0; j < 4; j++) {
                ulonglong2 x = *(const ulonglong2*)&ys[(rg*4+j)*68 + i4];
                a2[j] = f2_fma(w.x, x.x, a2[j]);
                c2[j] = f2_fma(w.y, x.y, c2[j]);
            }
        }
        float fr[4];
        #pragma unroll
        for (int j = 0; j < 4; j++) {
            fr[j] = f2_hadd(f2_add(a2[j], c2[j])) + prm[128 + o] + xr[j];
            xs[(rg*4+j)*68 + o] = fr[j];
        }
        __syncthreads();

        {
            float s1 = 0.f, s2 = 0.f;
            #pragma unroll
            for (int ii = 0; ii < 4; ii++) {
                float v = xs[rrS*68 + cS + ii*16]; s1 += v; s2 += v*v;
            }
            #pragma unroll
            for (int off = 8; off; off >>= 1) {
                s1 += __shfl_xor_sync(0xffffffffu, s1, off, 16);
                s2 += __shfl_xor_sync(0xffffffffu, s2, off, 16);
            }
            if (cS == 0) {
                float mu = s1 * (1.0f/64.0f);
                float var = s2 * (1.0f/64.0f) - mu*mu;
                mvS[rrS*2]     = mu;
                mvS[rrS*2 + 1] = rsqrtf(var + 1e-5f);
            }
        }
        __syncthreads();

        #pragma unroll
        for (int j = 0; j < 4; j++) {
            int rr = rg*4 + j;
            out[(rbase+rr)*EE + o] =
                (fr[j] - mvS[rr*2]) * mvS[rr*2+1] * prm[320 + o] + prm[384 + o];
        }
    }
}

__global__ __launch_bounds__(256) void tail_kernel(
    float* __restrict__ attn_out,
    const float* __restrict__ prev,
    const float* __restrict__ Wo, const float* __restrict__ bo,
    const float* __restrict__ ln1g, const float* __restrict__ ln1b,
    const float* __restrict__ W1, const float* __restrict__ b1,
    const float* __restrict__ W2, const float* __restrict__ b2,
    const float* __restrict__ ln2g, const float* __restrict__ ln2b,
    float* __restrict__ out)
{
    extern __shared__ float sm[];
    const int bid = blockIdx.x;
    if (bid & 1) {
        epilogue_body(sm, prev, Wo, bo, ln1g, ln1b, W1, b1, W2, b2,
                      ln2g, ln2b, out, bid >> 1);
    } else {
        attn2_body(sm, attn_out, bid >> 1);
    }
}

// ---------------------------------------------------------------------------
extern "C" void kernel_launch(void* const* d_in, const int* in_sizes, int n_in,
                              void* d_out, int out_size)
{
    const float* q    = (const float*)d_in[0];
    const float* k    = (const float*)d_in[1];
    const float* prev = (const float*)d_in[2];
    const float* Wq   = (const float*)d_in[3];
    const float* bq   = (const float*)d_in[4];
    const float* Wk   = (const float*)d_in[5];
    const float* bk   = (const float*)d_in[6];
    const float* Wv   = (const float*)d_in[7];
    const float* bv   = (const float*)d_in[8];
    const float* Wo   = (const float*)d_in[9];
    const float* bo   = (const float*)d_in[10];
    const float* ln1g = (const float*)d_in[11];
    const float* ln1b = (const float*)d_in[12];
    const float* W1   = (const float*)d_in[13];
    const float* b1   = (const float*)d_in[14];
    const float* W2   = (const float*)d_in[15];
    const float* b2   = (const float*)d_in[16];
    const float* ln2g = (const float*)d_in[17];
    const float* ln2b = (const float*)d_in[18];

    float* out      = (float*)d_out;
    float* attn_out = out + OUT_ELEMS;

    const int TAIL_SMEM = (3*64*68 + 2*16*68 + 32 + 7*64)*4; // 62848 B
    cudaFuncSetAttribute(tail_kernel,
        cudaFuncAttributeMaxDynamicSharedMemorySize, TAIL_SMEM);

    proj_kernel<<<dim3(NROWS/64, 3), 256>>>(q, k, Wq, bq, Wk, bk, Wv, bv);

    attn1_kernel<<<dim3(LL/64, BB), 128>>>();

    tail_kernel<<<2*(NROWS/64), 256, TAIL_SMEM>>>(
        attn_out, prev, Wo, bo, ln1g, ln1b, W1, b1, W2, b2, ln2g, ln2b, out);
}

// round 15
// speedup vs baseline: 1.2614x; 1.0124x over previous
#include <cuda_runtime.h>
#include <math.h>

// Problem constants
#define BB 64
#define LL 512
#define EE 64
#define HH 8
#define DD 8
#define NROWS (BB*LL)             // 32768
#define OUT_ELEMS (BB*LL*EE)      // 2097152

// Scratch (device globals; no allocation allowed)
__device__ float g_qh[NROWS*EE];
__device__ float g_kh[NROWS*EE];
__device__ float g_vh[NROWS*EE];
__device__ float g_ctx[NROWS*EE];
__device__ float g_zi[NROWS*HH];   // (1/Z)*0.125 per (row, head)

// ---------------------------------------------------------------------------
// Packed fp32x2 helpers (sm_103a FFMA2 path — only reachable via PTX f32x2)
// ---------------------------------------------------------------------------
__device__ __forceinline__ unsigned long long f2_pack(float lo, float hi) {
    unsigned long long r;
    asm("mov.b64 %0, {%1, %2};" : "=l"(r) : "f"(lo), "f"(hi));
    return r;
}
__device__ __forceinline__ void f2_unpack(float& lo, float& hi, unsigned long long v) {
    asm("mov.b64 {%0, %1}, %2;" : "=f"(lo), "=f"(hi) : "l"(v));
}
__device__ __forceinline__ unsigned long long f2_fma(
    unsigned long long a, unsigned long long b, unsigned long long c) {
    unsigned long long d;
    asm("fma.rn.f32x2 %0, %1, %2, %3;" : "=l"(d) : "l"(a), "l"(b), "l"(c));
    return d;
}
__device__ __forceinline__ unsigned long long f2_mul(
    unsigned long long a, unsigned long long b) {
    unsigned long long d;
    asm("mul.rn.f32x2 %0, %1, %2;" : "=l"(d) : "l"(a), "l"(b));
    return d;
}
__device__ __forceinline__ unsigned long long f2_add(
    unsigned long long a, unsigned long long b) {
    unsigned long long d;
    asm("add.rn.f32x2 %0, %1, %2;" : "=l"(d) : "l"(a), "l"(b));
    return d;
}
__device__ __forceinline__ float f2_hadd(unsigned long long v) {
    float lo, hi; f2_unpack(lo, hi, v); return lo + hi;
}
__device__ __forceinline__ float fast_ex2(float x) {
    float r;
    asm("ex2.approx.f32 %0, %1;" : "=f"(r) : "f"(x));
    return r;
}

// ---------------------------------------------------------------------------
// Kernel 1 (fused QKV proj): Y[r][o] = (sum_i X[r][i]*W[o][i] + b[o]) * oscale
// Weights hoisted to REGISTERS.  (measured: 39.2us)
// ---------------------------------------------------------------------------
__global__ __launch_bounds__(256) void proj_kernel(
    const float* __restrict__ qin, const float* __restrict__ kin,
    const float* __restrict__ Wq, const float* __restrict__ bq,
    const float* __restrict__ Wk, const float* __restrict__ bk,
    const float* __restrict__ Wv, const float* __restrict__ bv)
{
    __shared__ float Ws[64*68];
    __shared__ float bs[64];
    __shared__ float xs[16*68];

    const float* X; const float* W; const float* bias; float* Y; float oscale;
    if (blockIdx.y == 0) {
        X = qin; W = Wq; bias = bq; Y = g_qh;
        oscale = 0.51006969919583f;   // log2(e)/sqrt(D)
    } else if (blockIdx.y == 1) {
        X = kin; W = Wk; bias = bk; Y = g_kh; oscale = 1.0f;
    } else {
        X = kin; W = Wv; bias = bv; Y = g_vh; oscale = 1.0f;
    }

    const int t = threadIdx.x;
    for (int idx = t; idx < 1024; idx += 256) {
        int o = idx >> 4, i4 = (idx & 15) << 2;
        *(float4*)&Ws[o*68 + i4] = *(const float4*)&W[o*64 + i4];
    }
    if (t < 64) bs[t] = bias[t];
    __syncthreads();

    const int o = t & 63, rg = t >> 6;
    const int row0 = blockIdx.x * 64;

    unsigned long long wr[32];
    #pragma unroll
    for (int i = 0; i < 16; i++) {
        ulonglong2 w = *(const ulonglong2*)&Ws[o*68 + i*4];
        wr[2*i] = w.x; wr[2*i+1] = w.y;
    }
    const float bv_o = bs[o];

    for (int s = 0; s < 4; s++) {
        const int rbase = row0 + s*16;
        __syncthreads();
        {
            int rr = t >> 4, i4 = (t & 15) << 2;
            *(float4*)&xs[rr*68 + i4] = *(const float4*)&X[(rbase+rr)*64 + i4];
        }
        __syncthreads();
        unsigned long long a2[4] = {0ull,0ull,0ull,0ull};
        unsigned long long c2[4] = {0ull,0ull,0ull,0ull};
        #pragma unroll
        for (int i4 = 0; i4 < 16; i4++) {
            #pragma unroll
            for (int j = 0; j < 4; j++) {
                ulonglong2 x = *(const ulonglong2*)&xs[(rg*4+j)*68 + i4*4];
                a2[j] = f2_fma(wr[2*i4],   x.x, a2[j]);
                c2[j] = f2_fma(wr[2*i4+1], x.y, c2[j]);
            }
        }
        #pragma unroll
        for (int j = 0; j < 4; j++)
            Y[(rbase+rg*4+j)*64 + o] = (f2_hadd(f2_add(a2[j], c2[j])) + bv_o) * oscale;
    }
}

// ---------------------------------------------------------------------------
// Kernel 2a: attention pass 1 — proven R3 structure (measured ~150us).
// Block=(q-tile 64, batch), 128 threads, thread = (qg of 4 queries, head).
// Single pass: Z + unnormalized ctx; writes normalized ctx and zi*0.125.
// ---------------------------------------------------------------------------
__global__ __launch_bounds__(128) void attn1_kernel()
{
    __shared__ float ks[64*68];
    __shared__ float vs[64*68];

    const int b  = blockIdx.y;
    const int q0 = blockIdx.x * 64;
    const int t  = threadIdx.x;
    const int qg = t >> 3, h = t & 7;    // qg 0..15 (4 q each), h 0..7

    unsigned long long qp[4][4];
    #pragma unroll
    for (int j = 0; j < 4; j++) {
        const ulonglong2* qb =
            (const ulonglong2*)(g_qh + (size_t)(b*LL + q0 + qg*4 + j) * EE + h*8);
        ulonglong2 a = qb[0], c = qb[1];
        qp[j][0] = a.x; qp[j][1] = a.y; qp[j][2] = c.x; qp[j][3] = c.y;
    }

    float Z[4] = {0.f, 0.f, 0.f, 0.f};
    unsigned long long cx[4][4] = {{0ull,0ull,0ull,0ull},{0ull,0ull,0ull,0ull},
                                   {0ull,0ull,0ull,0ull},{0ull,0ull,0ull,0ull}};

    for (int c = 0; c < 8; c++) {
        __syncthreads();
        const float* kb = g_kh + (size_t)(b*LL + c*64) * EE;
        const float* vb = g_vh + (size_t)(b*LL + c*64) * EE;
        for (int idx = t; idx < 1024; idx += 128) {
            int m = idx >> 4, i4 = (idx & 15) << 2;
            *(float4*)&ks[m*68 + i4] = *(const float4*)(kb + m*EE + i4);
            *(float4*)&vs[m*68 + i4] = *(const float4*)(vb + m*EE + i4);
        }
        __syncthreads();
        #pragma unroll 2
        for (int m = 0; m < 64; m++) {
            ulonglong2 ka = *(const ulonglong2*)&ks[m*68 + h*8];
            ulonglong2 kc = *(const ulonglong2*)&ks[m*68 + h*8 + 4];
            ulonglong2 va = *(const ulonglong2*)&vs[m*68 + h*8];
            ulonglong2 vc = *(const ulonglong2*)&vs[m*68 + h*8 + 4];
            #pragma unroll
            for (int j = 0; j < 4; j++) {
                unsigned long long acc = f2_mul(qp[j][0], ka.x);
                acc = f2_fma(qp[j][1], ka.y, acc);
                acc = f2_fma(qp[j][2], kc.x, acc);
                acc = f2_fma(qp[j][3], kc.y, acc);
                float e = fast_ex2(f2_hadd(acc));
                Z[j] += e;
                unsigned long long pp = f2_pack(e, e);
                cx[j][0] = f2_fma(pp, va.x, cx[j][0]);
                cx[j][1] = f2_fma(pp, va.y, cx[j][1]);
                cx[j][2] = f2_fma(pp, vc.x, cx[j][2]);
                cx[j][3] = f2_fma(pp, vc.y, cx[j][3]);
            }
        }
    }

    #pragma unroll
    for (int j = 0; j < 4; j++) {
        float zi = 1.0f / Z[j];
        const size_t row = (size_t)(b*LL + q0 + qg*4 + j);
        float* cb = g_ctx + row * EE + h*8;
        float o[8];
        #pragma unroll
        for (int i = 0; i < 4; i++) {
            float lo, hi; f2_unpack(lo, hi, cx[j][i]);
            o[2*i] = lo * zi; o[2*i+1] = hi * zi;
        }
        *(float4*)(cb)     = make_float4(o[0], o[1], o[2], o[3]);
        *(float4*)(cb + 4) = make_float4(o[4], o[5], o[6], o[7]);
        g_zi[row*HH + h] = zi * 0.125f;
    }
}

// ---------------------------------------------------------------------------
// Tail: FUSED attn2 + epilogue in one launch. Blocks alternate roles.
// ---------------------------------------------------------------------------

// attn2 body: 256 threads; thread owns ONE query (all 8 heads), 4 threads
// per query striding m by 4. NEW: q-tile and zi staged through smem with
// coalesced loads (kills the ~29us/kernel uncoalesced-LDG setup).
__device__ __forceinline__ void attn2_body(float* sm, float* __restrict__ attn_out,
                                           int bx)
{
    float* ks = sm;               // 64*68 (q staging before first chunk)
    float* aw = sm + 64*68;       // 64*65 (zi staging before first chunk)

    const int b  = bx >> 3;
    const int q0 = (bx & 7) * 64;
    const int t  = threadIdx.x;
    const int q       = t & 63;   // local query
    const int quarter = t >> 6;   // m residue (uniform per warp)

    // ---- stage q-tile (contiguous 16KB) + zi (contiguous 2KB) coalesced ----
    {
        const float* qsrc = g_qh + (size_t)(b*LL + q0) * EE;
        for (int idx = t; idx < 1024; idx += 256) {
            int r = idx >> 4, i4 = (idx & 15) << 2;
            *(float4*)&ks[r*68 + i4] = *(const float4*)(qsrc + r*EE + i4);
        }
        const float* zsrc = g_zi + (size_t)(b*LL + q0) * HH;
        if (t < 128) {
            float4 z = *(const float4*)(zsrc + t*4);
            int r = t >> 1, off = (t & 1) * 4;
            *(float4*)&aw[r*12 + off] = z;   // stride 12 floats: 16B-aligned rows
        }
    }
    __syncthreads();

    unsigned long long qp[32];
    #pragma unroll
    for (int i = 0; i < 16; i++) {
        ulonglong2 v = *(const ulonglong2*)&ks[q*68 + i*4];
        qp[2*i] = v.x; qp[2*i+1] = v.y;
    }
    unsigned long long ziP[4];
    {
        float4 z0 = *(const float4*)&aw[q*12];
        float4 z1 = *(const float4*)&aw[q*12 + 4];
        ziP[0] = f2_pack(z0.x, z0.y); ziP[1] = f2_pack(z0.z, z0.w);
        ziP[2] = f2_pack(z1.x, z1.y); ziP[3] = f2_pack(z1.z, z1.w);
    }

    for (int c = 0; c < 8; c++) {
        __syncthreads();   // staging consumed / aw drained / ks consumed
        const float* kb = g_kh + (size_t)(b*LL + c*64) * EE;
        for (int idx = t; idx < 1024; idx += 256) {
            int m = idx >> 4, i4 = (idx & 15) << 2;
            *(float4*)&ks[m*68 + i4] = *(const float4*)(kb + m*EE + i4);
        }
        __syncthreads();

        #pragma unroll 2
        for (int mm = 0; mm < 16; mm++) {
            const int m = mm*4 + quarter;     // uniform per warp
            float e[8];
            #pragma unroll
            for (int hh = 0; hh < 8; hh++) {
                const ulonglong2* kr = (const ulonglong2*)&ks[m*68 + hh*8];
                ulonglong2 k0 = kr[0], k1 = kr[1];
                unsigned long long acc = f2_mul(qp[4*hh], k0.x);
                acc = f2_fma(qp[4*hh+1], k0.y, acc);
                acc = f2_fma(qp[4*hh+2], k1.x, acc);
                acc = f2_fma(qp[4*hh+3], k1.y, acc);
                e[hh] = fast_ex2(f2_hadd(acc));
            }
            unsigned long long acc = f2_mul(f2_pack(e[0], e[1]), ziP[0]);
            acc = f2_fma(f2_pack(e[2], e[3]), ziP[1], acc);
            acc = f2_fma(f2_pack(e[4], e[5]), ziP[2], acc);
            acc = f2_fma(f2_pack(e[6], e[7]), ziP[3], acc);
            aw[m*65 + q] = f2_hadd(acc);
        }
        __syncthreads();

        float* ob = attn_out + ((size_t)(b*LL) + q0) * LL + c*64;
        #pragma unroll
        for (int g = 0; g < 4; g++) {
            int idx = t + g*256;
            int mq = idx & 15, qq = idx >> 4;
            float4 v = make_float4(aw[(mq*4+0)*65 + qq], aw[(mq*4+1)*65 + qq],
                                   aw[(mq*4+2)*65 + qq], aw[(mq*4+3)*65 + qq]);
            *(float4*)(ob + (size_t)qq*LL + mq*4) = v;
        }
    }
}

__device__ __forceinline__ void epilogue_body(float* sm,
    const float* __restrict__ prev,
    const float* __restrict__ Wo, const float* __restrict__ bo,
    const float* __restrict__ ln1g, const float* __restrict__ ln1b,
    const float* __restrict__ W1, const float* __restrict__ b1,
    const float* __restrict__ W2, const float* __restrict__ b2,
    const float* __restrict__ ln2g, const float* __restrict__ ln2b,
    float* __restrict__ out, int bx)
{
    float* WoS = sm;                 // 64*68
    float* W1S = WoS + 64*68;
    float* W2S = W1S + 64*68;
    float* xs  = W2S + 64*68;        // 16*68
    float* ys  = xs + 16*68;         // 16*68
    float* mvS = ys + 16*68;         // 32
    float* prm = mvS + 32;           // 7*64

    const int t = threadIdx.x;
    for (int idx = t; idx < 1024; idx += 256) {
        int o = idx >> 4, i4 = (idx & 15) << 2;
        *(float4*)&WoS[o*68 + i4] = *(const float4*)&Wo[o*64 + i4];
        *(float4*)&W1S[o*68 + i4] = *(const float4*)&W1[o*64 + i4];
        *(float4*)&W2S[o*68 + i4] = *(const float4*)&W2[o*64 + i4];
    }
    if (t < 64) {
        prm[t]       = bo[t];   prm[64 + t]  = b1[t];  prm[128 + t] = b2[t];
        prm[192 + t] = ln1g[t]; prm[256 + t] = ln1b[t];
        prm[320 + t] = ln2g[t]; prm[384 + t] = ln2b[t];
    }

    const int o = t & 63, rg = t >> 6;
    const int row0 = bx * 64;
    const int rrS = t >> 4, cS = t & 15;

    for (int s = 0; s < 4; s++) {
        const int rbase = row0 + s*16;
        __syncthreads();
        {
            int rr = t >> 4, i4 = (t & 15) << 2;
            *(float4*)&xs[rr*68 + i4] = *(const float4*)&g_ctx[(rbase+rr)*EE + i4];
        }
        __syncthreads();

        unsigned long long a2[4] = {0ull,0ull,0ull,0ull};
        unsigned long long c2[4] = {0ull,0ull,0ull,0ull};
        #pragma unroll
        for (int i4 = 0; i4 < 64; i4 += 4) {
            ulonglong2 w = *(const ulonglong2*)&WoS[o*68 + i4];
            #pragma unroll
            for (int j = 0; j < 4; j++) {
                ulonglong2 x = *(const ulonglong2*)&xs[(rg*4+j)*68 + i4];
                a2[j] = f2_fma(w.x, x.x, a2[j]);
                c2[j] = f2_fma(w.y, x.y, c2[j]);
            }
        }
        #pragma unroll
        for (int j = 0; j < 4; j++) {
            float acc = f2_hadd(f2_add(a2[j], c2[j])) + prm[o];
            acc += prev[(rbase+rg*4+j)*EE + o];
            ys[(rg*4+j)*68 + o] = acc;
        }
        __syncthreads();

        {
            float s1 = 0.f, s2 = 0.f;
            #pragma unroll
            for (int ii = 0; ii < 4; ii++) {
                float v = ys[rrS*68 + cS + ii*16]; s1 += v; s2 += v*v;
            }
            #pragma unroll
            for (int off = 8; off; off >>= 1) {
                s1 += __shfl_xor_sync(0xffffffffu, s1, off, 16);
                s2 += __shfl_xor_sync(0xffffffffu, s2, off, 16);
            }
            if (cS == 0) {
                float mu = s1 * (1.0f/64.0f);
                float var = s2 * (1.0f/64.0f) - mu*mu;
                mvS[rrS*2]     = mu;
                mvS[rrS*2 + 1] = rsqrtf(var + 1e-5f);
            }
        }
        __syncthreads();

        float xr[4];
        #pragma unroll
        for (int j = 0; j < 4; j++) {
            int rr = rg*4 + j;
            float v = ys[rr*68 + o];
            float xn = (v - mvS[rr*2]) * mvS[rr*2+1] * prm[192 + o] + prm[256 + o];
            xr[j] = xn;
            xs[rr*68 + o] = xn;
        }
        __syncthreads();

        #pragma unroll
        for (int j = 0; j < 4; j++) { a2[j] = 0ull; c2[j] = 0ull; }
        #pragma unroll
        for (int i4 = 0; i4 < 64; i4 += 4) {
            ulonglong2 w = *(const ulonglong2*)&W1S[o*68 + i4];
            #pragma unroll
            for (int j = 0; j < 4; j++) {
                ulonglong2 x = *(const ulonglong2*)&xs[(rg*4+j)*68 + i4];
                a2[j] = f2_fma(w.x, x.x, a2[j]);
                c2[j] = f2_fma(w.y, x.y, c2[j]);
            }
        }
        #pragma unroll
        for (int j = 0; j < 4; j++)
            ys[(rg*4+j)*68 + o] = fmaxf(f2_hadd(f2_add(a2[j], c2[j])) + prm[64 + o], 0.f);
        __syncthreads();

        #pragma unroll
        for (int j = 0; j < 4; j++) { a2[j] = 0ull; c2[j] = 0ull; }
        #pragma unroll
        for (int i4 = 0; i4 < 64; i4 += 4) {
            ulonglong2 w = *(const ulonglong2*)&W2S[o*68 + i4];
            #pragma unroll
            for (int j = 0; j < 4; j++) {
                ulonglong2 x = *(const ulonglong2*)&ys[(rg*4+j)*68 + i4];
                a2[j] = f2_fma(w.x, x.x, a2[j]);
                c2[j] = f2_fma(w.y, x.y, c2[j]);
            }
        }
        float fr[4];
        #pragma unroll
        for (int j = 0; j < 4; j++) {
            fr[j] = f2_hadd(f2_add(a2[j], c2[j])) + prm[128 + o] + xr[j];
            xs[(rg*4+j)*68 + o] = fr[j];
        }
        __syncthreads();

        {
            float s1 = 0.f, s2 = 0.f;
            #pragma unroll
            for (int ii = 0; ii < 4; ii++) {
                float v = xs[rrS*68 + cS + ii*16]; s1 += v; s2 += v*v;
            }
            #pragma unroll
            for (int off = 8; off; off >>= 1) {
                s1 += __shfl_xor_sync(0xffffffffu, s1, off, 16);
                s2 += __shfl_xor_sync(0xffffffffu, s2, off, 16);
            }
            if (cS == 0) {
                float mu = s1 * (1.0f/64.0f);
                float var = s2 * (1.0f/64.0f) - mu*mu;
                mvS[rrS*2]     = mu;
                mvS[rrS*2 + 1] = rsqrtf(var + 1e-5f);
            }
        }
        __syncthreads();

        #pragma unroll
        for (int j = 0; j < 4; j++) {
            int rr = rg*4 + j;
            out[(rbase+rr)*EE + o] =
                (fr[j] - mvS[rr*2]) * mvS[rr*2+1] * prm[320 + o] + prm[384 + o];
        }
    }
}

__global__ __launch_bounds__(256) void tail_kernel(
    float* __restrict__ attn_out,
    const float* __restrict__ prev,
    const float* __restrict__ Wo, const float* __restrict__ bo,
    const float* __restrict__ ln1g, const float* __restrict__ ln1b,
    const float* __restrict__ W1, const float* __restrict__ b1,
    const float* __restrict__ W2, const float* __restrict__ b2,
    const float* __restrict__ ln2g, const float* __restrict__ ln2b,
    float* __restrict__ out)
{
    extern __shared__ float sm[];
    const int bid = blockIdx.x;
    if (bid & 1) {
        epilogue_body(sm, prev, Wo, bo, ln1g, ln1b, W1, b1, W2, b2,
                      ln2g, ln2b, out, bid >> 1);
    } else {
        attn2_body(sm, attn_out, bid >> 1);
    }
}

// ---------------------------------------------------------------------------
extern "C" void kernel_launch(void* const* d_in, const int* in_sizes, int n_in,
                              void* d_out, int out_size)
{
    const float* q    = (const float*)d_in[0];
    const float* k    = (const float*)d_in[1];
    const float* prev = (const float*)d_in[2];
    const float* Wq   = (const float*)d_in[3];
    const float* bq   = (const float*)d_in[4];
    const float* Wk   = (const float*)d_in[5];
    const float* bk   = (const float*)d_in[6];
    const float* Wv   = (const float*)d_in[7];
    const float* bv   = (const float*)d_in[8];
    const float* Wo   = (const float*)d_in[9];
    const float* bo   = (const float*)d_in[10];
    const float* ln1g = (const float*)d_in[11];
    const float* ln1b = (const float*)d_in[12];
    const float* W1   = (const float*)d_in[13];
    const float* b1   = (const float*)d_in[14];
    const float* W2   = (const float*)d_in[15];
    const float* b2   = (const float*)d_in[16];
    const float* ln2g = (const float*)d_in[17];
    const float* ln2b = (const float*)d_in[18];

    float* out      = (float*)d_out;
    float* attn_out = out + OUT_ELEMS;

    const int TAIL_SMEM = (3*64*68 + 2*16*68 + 32 + 7*64)*4; // 62848 B
    cudaFuncSetAttribute(tail_kernel,
        cudaFuncAttributeMaxDynamicSharedMemorySize, TAIL_SMEM);

    proj_kernel<<<dim3(NROWS/64, 3), 256>>>(q, k, Wq, bq, Wk, bk, Wv, bv);

    attn1_kernel<<<dim3(LL/64, BB), 128>>>();

    tail_kernel<<<2*(NROWS/64), 256, TAIL_SMEM>>>(
        attn_out, prev, Wo, bo, ln1g, ln1b, W1, b1, W2, b2, ln2g, ln2b, out);
}